// round 1
// baseline (speedup 1.0000x reference)
#include <cuda_runtime.h>

#define NNZ_CONST 524288
#define N_MENTIONS 65536
#define D 256
#define LANES 64              // threads per mention group (64 x float4 = 256 floats)
#define GROUPS_PER_BLOCK 4    // 256 threads per block

__global__ __launch_bounds__(LANES * GROUPS_PER_BLOCK)
void mention_segsum_kernel(const float4* __restrict__ token_ft,   // [N_TOKENS, 64] as float4
                           const int*    __restrict__ token_code, // [NNZ]
                           const int*    __restrict__ spm_rows,   // [NNZ] sorted
                           const float*  __restrict__ spm_vals,   // [NNZ]
                           float4*       __restrict__ out,        // [N_MENTIONS, 64] as float4
                           int nnz)
{
    const int group = blockIdx.x * GROUPS_PER_BLOCK + (threadIdx.x / LANES);
    const int lane  = threadIdx.x & (LANES - 1);
    if (group >= N_MENTIONS) return;

    // Binary search: segment [start, end) with spm_rows[j] == group.
    // Index array is tiny (2 MB) and L2-resident after first wave; redundant
    // per-thread search is ~2x19 cheap iterations, no sync needed.
    int lo = 0, hi = nnz;
    while (lo < hi) {
        int mid = (lo + hi) >> 1;
        if (__ldg(spm_rows + mid) < group) lo = mid + 1; else hi = mid;
    }
    const int start = lo;
    hi = nnz;
    while (lo < hi) {
        int mid = (lo + hi) >> 1;
        if (__ldg(spm_rows + mid) < group + 1) lo = mid + 1; else hi = mid;
    }
    const int end = lo;

    float4 acc = make_float4(0.f, 0.f, 0.f, 0.f);

    // Unroll-by-2 over the segment for memory-level parallelism within a group.
    int j = start;
    for (; j + 1 < end; j += 2) {
        const int   c0 = __ldg(token_code + j);
        const int   c1 = __ldg(token_code + j + 1);
        const float v0 = __ldg(spm_vals + j);
        const float v1 = __ldg(spm_vals + j + 1);
        const float4 f0 = __ldg(token_ft + (size_t)c0 * (D / 4) + lane);
        const float4 f1 = __ldg(token_ft + (size_t)c1 * (D / 4) + lane);
        acc.x += v0 * f0.x + v1 * f1.x;
        acc.y += v0 * f0.y + v1 * f1.y;
        acc.z += v0 * f0.z + v1 * f1.z;
        acc.w += v0 * f0.w + v1 * f1.w;
    }
    if (j < end) {
        const int   c0 = __ldg(token_code + j);
        const float v0 = __ldg(spm_vals + j);
        const float4 f0 = __ldg(token_ft + (size_t)c0 * (D / 4) + lane);
        acc.x += v0 * f0.x;
        acc.y += v0 * f0.y;
        acc.z += v0 * f0.z;
        acc.w += v0 * f0.w;
    }

    // One coalesced 1KB store per mention row; empty segments write zeros,
    // so the poisoned output buffer is fully initialized.
    out[(size_t)group * (D / 4) + lane] = acc;
}

extern "C" void kernel_launch(void* const* d_in, const int* in_sizes, int n_in,
                              void* d_out, int out_size)
{
    const float* token_ft   = (const float*)d_in[0]; // [262144, 256] f32
    const int*   token_code = (const int*)  d_in[1]; // [524288] i32
    const int*   spm_rows   = (const int*)  d_in[2]; // [524288] i32 sorted
    const float* spm_vals   = (const float*)d_in[3]; // [524288] f32
    float*       out        = (float*)d_out;         // [65536, 256] f32

    const int nnz = in_sizes[1];

    const int threads = LANES * GROUPS_PER_BLOCK;                  // 256
    const int blocks  = (N_MENTIONS + GROUPS_PER_BLOCK - 1) / GROUPS_PER_BLOCK; // 16384

    mention_segsum_kernel<<<blocks, threads>>>(
        (const float4*)token_ft, token_code, spm_rows, spm_vals,
        (float4*)out, nnz);
}

// round 2
// speedup vs baseline: 1.6492x; 1.6492x over previous
#include <cuda_runtime.h>

#define N_MENTIONS 65536
#define D 256
#define LANES 64              // threads per mention group (64 x float4 = 256 floats)
#define GROUPS_PER_BLOCK 4    // 256 threads per block

// Scratch: CSR row pointers built each launch (allocation-free requirement).
__device__ int g_row_ptr[N_MENTIONS + 1];

// Prologue: boundary-fill row_ptr from sorted COO rows.
// Thread j owns nnz index j; fills row_ptr for every row starting at j.
__global__ void build_rowptr_kernel(const int* __restrict__ spm_rows, int nnz)
{
    int j = blockIdx.x * blockDim.x + threadIdx.x;
    if (j >= nnz) return;
    const int r  = __ldg(spm_rows + j);
    const int rp = (j == 0) ? -1 : __ldg(spm_rows + j - 1);
    // Rows (rp, r] all start at j. Gaps are rare (Poisson(8) segments).
    for (int row = rp + 1; row <= r; ++row) g_row_ptr[row] = j;
    if (j == nnz - 1) {
        for (int row = r + 1; row <= N_MENTIONS; ++row) g_row_ptr[row] = nnz;
    }
}

__global__ __launch_bounds__(LANES * GROUPS_PER_BLOCK)
void mention_segsum_kernel(const float4* __restrict__ token_ft,   // [N_TOKENS, 64] float4
                           const int*    __restrict__ token_code, // [NNZ]
                           const float*  __restrict__ spm_vals,   // [NNZ]
                           float4*       __restrict__ out)        // [N_MENTIONS, 64] float4
{
    const int group = blockIdx.x * GROUPS_PER_BLOCK + (threadIdx.x / LANES);
    const int lane  = threadIdx.x & (LANES - 1);
    if (group >= N_MENTIONS) return;

    const int start = g_row_ptr[group];
    const int end   = g_row_ptr[group + 1];

    float4 acc = make_float4(0.f, 0.f, 0.f, 0.f);

    // 4-wide unroll: batch the index/value loads, then issue 4 independent
    // 1KB row gathers so the LSU has deep MLP per warp.
    int j = start;
    for (; j + 3 < end; j += 4) {
        const int   c0 = __ldg(token_code + j);
        const int   c1 = __ldg(token_code + j + 1);
        const int   c2 = __ldg(token_code + j + 2);
        const int   c3 = __ldg(token_code + j + 3);
        const float v0 = __ldg(spm_vals + j);
        const float v1 = __ldg(spm_vals + j + 1);
        const float v2 = __ldg(spm_vals + j + 2);
        const float v3 = __ldg(spm_vals + j + 3);
        const float4 f0 = __ldg(token_ft + (size_t)c0 * (D / 4) + lane);
        const float4 f1 = __ldg(token_ft + (size_t)c1 * (D / 4) + lane);
        const float4 f2 = __ldg(token_ft + (size_t)c2 * (D / 4) + lane);
        const float4 f3 = __ldg(token_ft + (size_t)c3 * (D / 4) + lane);
        acc.x += v0 * f0.x + v1 * f1.x + v2 * f2.x + v3 * f3.x;
        acc.y += v0 * f0.y + v1 * f1.y + v2 * f2.y + v3 * f3.y;
        acc.z += v0 * f0.z + v1 * f1.z + v2 * f2.z + v3 * f3.z;
        acc.w += v0 * f0.w + v1 * f1.w + v2 * f2.w + v3 * f3.w;
    }
    for (; j < end; ++j) {
        const int   c0 = __ldg(token_code + j);
        const float v0 = __ldg(spm_vals + j);
        const float4 f0 = __ldg(token_ft + (size_t)c0 * (D / 4) + lane);
        acc.x += v0 * f0.x;
        acc.y += v0 * f0.y;
        acc.z += v0 * f0.z;
        acc.w += v0 * f0.w;
    }

    // One coalesced 1KB store per mention row; empty segments write zeros.
    out[(size_t)group * (D / 4) + lane] = acc;
}

extern "C" void kernel_launch(void* const* d_in, const int* in_sizes, int n_in,
                              void* d_out, int out_size)
{
    const float* token_ft   = (const float*)d_in[0]; // [262144, 256] f32
    const int*   token_code = (const int*)  d_in[1]; // [524288] i32
    const int*   spm_rows   = (const int*)  d_in[2]; // [524288] i32 sorted
    const float* spm_vals   = (const float*)d_in[3]; // [524288] f32
    float*       out        = (float*)d_out;         // [65536, 256] f32

    const int nnz = in_sizes[1];

    build_rowptr_kernel<<<(nnz + 255) / 256, 256>>>(spm_rows, nnz);

    const int threads = LANES * GROUPS_PER_BLOCK;                                 // 256
    const int blocks  = (N_MENTIONS + GROUPS_PER_BLOCK - 1) / GROUPS_PER_BLOCK;   // 16384

    mention_segsum_kernel<<<blocks, threads>>>(
        (const float4*)token_ft, token_code, spm_vals, (float4*)out);
}

// round 3
// speedup vs baseline: 1.6926x; 1.0263x over previous
#include <cuda_runtime.h>

#define N_MENTIONS 65536
#define D 256
#define LANES 64              // threads per mention group (64 x float4 = 256 floats)
#define GROUPS_PER_BLOCK 4    // 256 threads per block

// Scratch: CSR row pointers built each launch (allocation-free requirement).
__device__ int g_row_ptr[N_MENTIONS + 1];

// Prologue: boundary-fill row_ptr from sorted COO rows, int4-vectorized.
// Thread t owns nnz indices [4t, 4t+4).
__global__ void build_rowptr_kernel(const int4* __restrict__ spm_rows4, int nnz)
{
    int t = blockIdx.x * blockDim.x + threadIdx.x;
    int j0 = t * 4;
    if (j0 >= nnz) return;

    const int4 r4 = __ldg(spm_rows4 + t);
    // previous element (last of preceding int4), or -1 at the very start
    int rp;
    if (j0 == 0) rp = -1;
    else         rp = __ldg(((const int*)spm_rows4) + j0 - 1);

    int rr[4] = {r4.x, r4.y, r4.z, r4.w};
    #pragma unroll
    for (int k = 0; k < 4; ++k) {
        const int r = rr[k];
        for (int row = rp + 1; row <= r; ++row) g_row_ptr[row] = j0 + k;
        rp = r;
    }
    if (j0 + 4 >= nnz) {
        for (int row = rp + 1; row <= N_MENTIONS; ++row) g_row_ptr[row] = nnz;
    }
}

__global__ __launch_bounds__(LANES * GROUPS_PER_BLOCK)
void mention_segsum_kernel(const float4* __restrict__ token_ft,   // [N_TOKENS, 64] float4
                           const int*    __restrict__ token_code, // [NNZ]
                           const float*  __restrict__ spm_vals,   // [NNZ]
                           float4*       __restrict__ out)        // [N_MENTIONS, 64] float4
{
    const int group = blockIdx.x * GROUPS_PER_BLOCK + (threadIdx.x / LANES);
    const int lane  = threadIdx.x & (LANES - 1);
    if (group >= N_MENTIONS) return;

    const int start = g_row_ptr[group];
    const int end   = g_row_ptr[group + 1];

    float4 acc = make_float4(0.f, 0.f, 0.f, 0.f);

    // 4-wide unroll: 4 independent 1KB row gathers in flight per warp.
    // __ldcg: L2-only caching — gathered rows have no intra-SM reuse, keep L1 clean.
    int j = start;
    for (; j + 3 < end; j += 4) {
        const int   c0 = __ldg(token_code + j);
        const int   c1 = __ldg(token_code + j + 1);
        const int   c2 = __ldg(token_code + j + 2);
        const int   c3 = __ldg(token_code + j + 3);
        const float v0 = __ldg(spm_vals + j);
        const float v1 = __ldg(spm_vals + j + 1);
        const float v2 = __ldg(spm_vals + j + 2);
        const float v3 = __ldg(spm_vals + j + 3);
        const float4 f0 = __ldcg(token_ft + (size_t)c0 * (D / 4) + lane);
        const float4 f1 = __ldcg(token_ft + (size_t)c1 * (D / 4) + lane);
        const float4 f2 = __ldcg(token_ft + (size_t)c2 * (D / 4) + lane);
        const float4 f3 = __ldcg(token_ft + (size_t)c3 * (D / 4) + lane);
        acc.x += v0 * f0.x + v1 * f1.x + v2 * f2.x + v3 * f3.x;
        acc.y += v0 * f0.y + v1 * f1.y + v2 * f2.y + v3 * f3.y;
        acc.z += v0 * f0.z + v1 * f1.z + v2 * f2.z + v3 * f3.z;
        acc.w += v0 * f0.w + v1 * f1.w + v2 * f2.w + v3 * f3.w;
    }
    // 2-wide tail step (halves the serialized tail latency vs 3x scalar)
    if (j + 1 < end) {
        const int   c0 = __ldg(token_code + j);
        const int   c1 = __ldg(token_code + j + 1);
        const float v0 = __ldg(spm_vals + j);
        const float v1 = __ldg(spm_vals + j + 1);
        const float4 f0 = __ldcg(token_ft + (size_t)c0 * (D / 4) + lane);
        const float4 f1 = __ldcg(token_ft + (size_t)c1 * (D / 4) + lane);
        acc.x += v0 * f0.x + v1 * f1.x;
        acc.y += v0 * f0.y + v1 * f1.y;
        acc.z += v0 * f0.z + v1 * f1.z;
        acc.w += v0 * f0.w + v1 * f1.w;
        j += 2;
    }
    if (j < end) {
        const int   c0 = __ldg(token_code + j);
        const float v0 = __ldg(spm_vals + j);
        const float4 f0 = __ldcg(token_ft + (size_t)c0 * (D / 4) + lane);
        acc.x += v0 * f0.x;
        acc.y += v0 * f0.y;
        acc.z += v0 * f0.z;
        acc.w += v0 * f0.w;
    }

    // Streaming store (evict-first): keep the 64MB output from evicting
    // token-table lines in L2. One coalesced 1KB store per mention row.
    __stcs(out + (size_t)group * (D / 4) + lane, acc);
}

extern "C" void kernel_launch(void* const* d_in, const int* in_sizes, int n_in,
                              void* d_out, int out_size)
{
    const float* token_ft   = (const float*)d_in[0]; // [262144, 256] f32
    const int*   token_code = (const int*)  d_in[1]; // [524288] i32
    const int*   spm_rows   = (const int*)  d_in[2]; // [524288] i32 sorted
    const float* spm_vals   = (const float*)d_in[3]; // [524288] f32
    float*       out        = (float*)d_out;         // [65536, 256] f32

    const int nnz = in_sizes[1];

    const int pro_threads = 256;
    const int pro_work    = (nnz + 3) / 4;
    build_rowptr_kernel<<<(pro_work + pro_threads - 1) / pro_threads, pro_threads>>>(
        (const int4*)spm_rows, nnz);

    const int threads = LANES * GROUPS_PER_BLOCK;                                 // 256
    const int blocks  = (N_MENTIONS + GROUPS_PER_BLOCK - 1) / GROUPS_PER_BLOCK;   // 16384

    mention_segsum_kernel<<<blocks, threads>>>(
        (const float4*)token_ft, token_code, spm_vals, (float4*)out);
}